// round 6
// baseline (speedup 1.0000x reference)
#include <cuda_runtime.h>
#include <cstdint>

#define FULL_MASK 0xFFFFFFFFu
#define NQ 8
#define DEPTH 3
#define FDIM 512
#define NCLS 10

// Deferred-CNOT masks (GF(2)); layout p = (lane<<3)|r, r = qubit bits 0..2.
// parity table for 3-bit values: 0x96
template<int PM, int W>
__device__ __forceinline__ void gate2(float ar[2][8], float ai[2][8],
                                      float4 A, float4 Bv, int lane)
{
    constexpr int pr = PM & 7;
    constexpr int pl = PM >> 3;
    constexpr int wr = W & 7;
    constexpr int wl = W >> 3;
    const float2 u00 = make_float2(A.x, A.y),  u01 = make_float2(A.z, A.w);
    const float2 u10 = make_float2(Bv.x, Bv.y), u11 = make_float2(Bv.z, Bv.w);
    bool bL = (wl != 0) && ((__popc(lane & wl) & 1) != 0);
    float2 oA = bL ? u11 : u00, pA = bL ? u10 : u01;
    float2 oB = bL ? u00 : u11, pB = bL ? u01 : u10;

    if constexpr (pl == 0) {
        // register-resident pairing, both elems (no shuffles)
        #pragma unroll
        for (int e = 0; e < 2; e++) {
            #pragma unroll
            for (int r = 0; r < 8; r++) {
                if (((0x96 >> (r & wr)) & 1) == 0) {   // base of pair (compile-time)
                    const int r1 = r ^ pr;
                    float a0r = ar[e][r],  a0i = ai[e][r];
                    float a1r = ar[e][r1], a1i = ai[e][r1];
                    ar[e][r]  = oA.x*a0r - oA.y*a0i + pA.x*a1r - pA.y*a1i;
                    ai[e][r]  = oA.x*a0i + oA.y*a0r + pA.x*a1i + pA.y*a1r;
                    ar[e][r1] = oB.x*a1r - oB.y*a1i + pB.x*a0r - pB.y*a0i;
                    ai[e][r1] = oB.x*a1i + oB.y*a1r + pB.x*a0i + pB.y*a0r;
                }
            }
        }
    } else if constexpr (pr == 0) {
        // same r slot in lane^pl: stream one r, both elems (4 temps, 4 indep SHFLs)
        #pragma unroll
        for (int r = 0; r < 8; r++) {
            float t0r = __shfl_xor_sync(FULL_MASK, ar[0][r], pl);
            float t0i = __shfl_xor_sync(FULL_MASK, ai[0][r], pl);
            float t1r = __shfl_xor_sync(FULL_MASK, ar[1][r], pl);
            float t1i = __shfl_xor_sync(FULL_MASK, ai[1][r], pl);
            const bool pb = ((0x96 >> (r & wr)) & 1) != 0;   // compile-time
            float2 o = pb ? oB : oA;
            float2 p = pb ? pB : pA;
            float n0r = o.x*ar[0][r] - o.y*ai[0][r] + p.x*t0r - p.y*t0i;
            float n0i = o.x*ai[0][r] + o.y*ar[0][r] + p.x*t0i + p.y*t0r;
            float n1r = o.x*ar[1][r] - o.y*ai[1][r] + p.x*t1r - p.y*t1i;
            float n1i = o.x*ai[1][r] + o.y*ar[1][r] + p.x*t1i + p.y*t1r;
            ar[0][r] = n0r; ai[0][r] = n0i;
            ar[1][r] = n1r; ai[1][r] = n1i;
        }
    } else {
        // partner = r^pr in lane^pl: per-elem, per-pair streaming (4 temps)
        #pragma unroll
        for (int e = 0; e < 2; e++) {
            #pragma unroll
            for (int r = 0; r < 8; r++) {
                if (r < (r ^ pr)) {                   // compile-time pair rep
                    const int r1 = r ^ pr;
                    float sr0 = __shfl_xor_sync(FULL_MASK, ar[e][r1], pl);
                    float si0 = __shfl_xor_sync(FULL_MASK, ai[e][r1], pl);
                    float sr1 = __shfl_xor_sync(FULL_MASK, ar[e][r],  pl);
                    float si1 = __shfl_xor_sync(FULL_MASK, ai[e][r],  pl);
                    const bool pb0 = ((0x96 >> (r  & wr)) & 1) != 0;
                    const bool pb1 = ((0x96 >> (r1 & wr)) & 1) != 0;
                    float2 o0 = pb0 ? oB : oA, p0 = pb0 ? pB : pA;
                    float2 o1 = pb1 ? oB : oA, p1 = pb1 ? pB : pA;
                    float nr0 = o0.x*ar[e][r]  - o0.y*ai[e][r]  + p0.x*sr0 - p0.y*si0;
                    float ni0 = o0.x*ai[e][r]  + o0.y*ar[e][r]  + p0.x*si0 + p0.y*sr0;
                    float nr1 = o1.x*ar[e][r1] - o1.y*ai[e][r1] + p1.x*sr1 - p1.y*si1;
                    float ni1 = o1.x*ai[e][r1] + o1.y*ar[e][r1] + p1.x*si1 + p1.y*sr1;
                    ar[e][r]  = nr0; ai[e][r]  = ni0;
                    ar[e][r1] = nr1; ai[e][r1] = ni1;
                }
            }
        }
    }
}

__global__ void __launch_bounds__(256, 4) qiskit_head_kernel(
    const float* __restrict__ x,       // (B, 512)
    const float* __restrict__ proj_w,  // (8, 512)
    const float* __restrict__ qnn_w,   // (72,)
    const float* __restrict__ out_w,   // (10, 8)
    const float* __restrict__ out_b,   // (10,)
    float* __restrict__ out,           // (B, 10)
    int B)
{
    __shared__ __align__(16) float s_pw[NQ * FDIM];   // 16 KB
    __shared__ float4 s_g4[DEPTH * NQ][2];
    __shared__ float  s_ow[NCLS * NQ];
    __shared__ float  s_ob[NCLS];

    const int tid  = threadIdx.x;
    const int lane = tid & 31;
    const int warp = tid >> 5;

    #pragma unroll 4
    for (int i = tid; i < NQ * FDIM; i += 256) s_pw[i] = proj_w[i];
    if (tid < NCLS * NQ) s_ow[tid] = out_w[tid];
    if (tid < NCLS)      s_ob[tid] = out_b[tid];
    if (tid < DEPTH * NQ) {
        float w0 = qnn_w[tid * 3 + 0];
        float w1 = qnn_w[tid * 3 + 1];
        float w2 = qnn_w[tid * 3 + 2];
        float c0, s0, c1, s1, c2, s2;
        sincosf(0.5f * w0, &s0, &c0);
        sincosf(0.5f * w1, &s1, &c1);
        sincosf(0.5f * w2, &s2, &c2);
        float2 A00 = { c1 * c0,  s1 * s0};
        float2 A01 = {-s1 * c0, -c1 * s0};
        float2 A10 = { s1 * c0, -c1 * s0};
        float2 A11 = { c1 * c0, -s1 * s0};
        float2 g00 = make_float2(c2 * A00.x + s2 * A10.y, c2 * A00.y - s2 * A10.x);
        float2 g01 = make_float2(c2 * A01.x + s2 * A11.y, c2 * A01.y - s2 * A11.x);
        float2 g10 = make_float2(c2 * A10.x + s2 * A00.y, c2 * A10.y - s2 * A00.x);
        float2 g11 = make_float2(c2 * A11.x + s2 * A01.y, c2 * A11.y - s2 * A01.x);
        s_g4[tid][0] = make_float4(g00.x, g00.y, g01.x, g01.y);
        s_g4[tid][1] = make_float4(g10.x, g10.y, g11.x, g11.y);
    }
    __syncthreads();

    auto mrg = [&](float a, float b, int dist) {
        float c = (lane & dist) ? b : a;
        float d = (lane & dist) ? a : b;
        return c + __shfl_xor_sync(FULL_MASK, d, dist);
    };
    auto srcLane = [](int q) { return ((q & 1) << 4) | (((q >> 1) & 1) << 3) | (((q >> 2) & 1) << 2); };

    const int b0 = (blockIdx.x * 8 + warp) * 2;
    const int b1 = b0 + 1;
    if (b0 >= B) return;
    const bool v1 = (b1 < B);

    // ---- projection: acc[e][q] = x[b_e] . proj_w[q] ----
    float acc[2][NQ];
    #pragma unroll
    for (int e = 0; e < 2; e++)
        #pragma unroll
        for (int q = 0; q < NQ; q++) acc[e][q] = 0.f;

    const float4* xr0 = (const float4*)(x + (size_t)b0 * FDIM);
    const float4* xr1 = (const float4*)(x + (size_t)(v1 ? b1 : b0) * FDIM);
    #pragma unroll
    for (int ch = 0; ch < 4; ch++) {
        float4 xv0 = xr0[ch * 32 + lane];
        float4 xv1 = xr1[ch * 32 + lane];
        #pragma unroll
        for (int q = 0; q < NQ; q++) {
            float4 wv = *(const float4*)&s_pw[q * FDIM + ch * 128 + lane * 4];
            acc[0][q] += xv0.x*wv.x + xv0.y*wv.y + xv0.z*wv.z + xv0.w*wv.w;
            acc[1][q] += xv1.x*wv.x + xv1.y*wv.y + xv1.z*wv.z + xv1.w*wv.w;
        }
    }
    // dual 9-shfl multi-reduce (interleaved)
    float cv[2], sv[2];
    {
        float a0m0 = mrg(acc[0][0], acc[0][1], 16), a1m0 = mrg(acc[1][0], acc[1][1], 16);
        float a0m1 = mrg(acc[0][2], acc[0][3], 16), a1m1 = mrg(acc[1][2], acc[1][3], 16);
        float a0m2 = mrg(acc[0][4], acc[0][5], 16), a1m2 = mrg(acc[1][4], acc[1][5], 16);
        float a0m3 = mrg(acc[0][6], acc[0][7], 16), a1m3 = mrg(acc[1][6], acc[1][7], 16);
        float a0n0 = mrg(a0m0, a0m1, 8), a1n0 = mrg(a1m0, a1m1, 8);
        float a0n1 = mrg(a0m2, a0m3, 8), a1n1 = mrg(a1m2, a1m3, 8);
        float f0 = mrg(a0n0, a0n1, 4),   f1 = mrg(a1n0, a1n1, 4);
        f0 += __shfl_xor_sync(FULL_MASK, f0, 2); f1 += __shfl_xor_sync(FULL_MASK, f1, 2);
        f0 += __shfl_xor_sync(FULL_MASK, f0, 1); f1 += __shfl_xor_sync(FULL_MASK, f1, 1);
        float h0 = tanhf(f0) * 0.78539816339744830962f;
        float h1 = tanhf(f1) * 0.78539816339744830962f;
        __sincosf(h0, &sv[0], &cv[0]);
        __sincosf(h1, &sv[1], &cv[1]);
    }

    // ---- state after encoding + layer-0 gates: product state ----
    // Angle cos/sin broadcast inlined per qubit: no cq/sq arrays (register diet).
    float ar[2][8], ai[2][8];
    #pragma unroll
    for (int e = 0; e < 2; e++) {
        float Lr = 1.f, Li = 0.f;
        #pragma unroll
        for (int k = 0; k < 5; k++) {
            const int q = k + 3;
            const int sl = srcLane(q);
            float c = __shfl_sync(FULL_MASK, cv[e], sl);
            float s = __shfl_sync(FULL_MASK, sv[e], sl);
            const int bit = (lane >> k) & 1;
            float4 V = s_g4[q][bit];
            float wx = V.x * c + V.z * s;
            float wy = V.y * c + V.w * s;
            float nr = Lr*wx - Li*wy;
            float ni = Lr*wy + Li*wx;
            Lr = nr; Li = ni;
        }
        {
            float c = __shfl_sync(FULL_MASK, cv[e], srcLane(0));
            float s = __shfl_sync(FULL_MASK, sv[e], srcLane(0));
            float4 A0 = s_g4[0][0], B0 = s_g4[0][1];
            float a0x = A0.x*c + A0.z*s, a0y = A0.y*c + A0.w*s;
            float b0x = B0.x*c + B0.z*s, b0y = B0.y*c + B0.w*s;
            ar[e][0] = Lr*a0x - Li*a0y;  ai[e][0] = Lr*a0y + Li*a0x;
            ar[e][1] = Lr*b0x - Li*b0y;  ai[e][1] = Lr*b0y + Li*b0x;
        }
        {
            float c = __shfl_sync(FULL_MASK, cv[e], srcLane(1));
            float s = __shfl_sync(FULL_MASK, sv[e], srcLane(1));
            float4 A1 = s_g4[1][0], B1 = s_g4[1][1];
            float a1x = A1.x*c + A1.z*s, a1y = A1.y*c + A1.w*s;
            float b1x = B1.x*c + B1.z*s, b1y = B1.y*c + B1.w*s;
            #pragma unroll
            for (int r = 0; r < 2; r++) {
                float tr = ar[e][r], ti = ai[e][r];
                ar[e][r + 2] = tr*b1x - ti*b1y;  ai[e][r + 2] = tr*b1y + ti*b1x;
                ar[e][r]     = tr*a1x - ti*a1y;  ai[e][r]     = tr*a1y + ti*a1x;
            }
        }
        {
            float c = __shfl_sync(FULL_MASK, cv[e], srcLane(2));
            float s = __shfl_sync(FULL_MASK, sv[e], srcLane(2));
            float4 A2 = s_g4[2][0], B2 = s_g4[2][1];
            float a2x = A2.x*c + A2.z*s, a2y = A2.y*c + A2.w*s;
            float b2x = B2.x*c + B2.z*s, b2y = B2.y*c + B2.w*s;
            #pragma unroll
            for (int r = 0; r < 4; r++) {
                float tr = ar[e][r], ti = ai[e][r];
                ar[e][r + 4] = tr*b2x - ti*b2y;  ai[e][r + 4] = tr*b2y + ti*b2x;
                ar[e][r]     = tr*a2x - ti*a2y;  ai[e][r]     = tr*a2y + ti*a2x;
            }
        }
    }

    // ---- layers 1,2 with deferred-CNOT masks ----
    #define GATE(idx, PMv, Wv) gate2<PMv, Wv>(ar, ai, s_g4[idx][0], s_g4[idx][1], lane)
    // layer 1 (phi = C)
    GATE(8,  0x03, 0xFE); GATE(9,  0x06, 0x03); GATE(10, 0x0C, 0x07); GATE(11, 0x18, 0x0F);
    GATE(12, 0x30, 0x1F); GATE(13, 0x60, 0x3F); GATE(14, 0xC0, 0x7F); GATE(15, 0x83, 0xFF);
    // layer 2 (phi = C^2)
    GATE(16, 0x05, 0xAB); GATE(17, 0x0A, 0xFD); GATE(18, 0x14, 0xFA); GATE(19, 0x28, 0xF5);
    GATE(20, 0x50, 0xEA); GATE(21, 0xA0, 0xD5); GATE(22, 0x43, 0xAA); GATE(23, 0x86, 0x55);
    #undef GATE

    // ---- PauliZ via Walsh-Hadamard of |amp|^2 (phi = C^3) ----
    float z[2][8];
    #pragma unroll
    for (int e = 0; e < 2; e++) {
        float S[8];
        #pragma unroll
        for (int r = 0; r < 8; r++) S[r] = ar[e][r]*ar[e][r] + ai[e][r]*ai[e][r];
        #pragma unroll
        for (int st = 0; st < 3; st++) {
            const int d = 1 << st;
            #pragma unroll
            for (int r = 0; r < 8; r++) {
                if (!(r & d)) {
                    float a = S[r] + S[r + d];
                    float bm = S[r] - S[r + d];
                    S[r] = a; S[r + d] = bm;
                }
            }
        }
        auto sg = [&](int wl, float v) { return (__popc(lane & wl) & 1) ? -v : v; };
        z[e][0] = sg(0x06, S[2]); z[e][1] = sg(0x0A, S[6]);
        z[e][2] = sg(0x15, S[4]); z[e][3] = sg(0x0B, S[1]);
        z[e][4] = sg(0x16, S[3]); z[e][5] = sg(0x0C, S[6]);
        z[e][6] = sg(0x19, S[4]); z[e][7] = sg(0x13, S[1]);
    }
    float f0, f1;
    {
        float a0m0 = mrg(z[0][0], z[0][1], 16), a1m0 = mrg(z[1][0], z[1][1], 16);
        float a0m1 = mrg(z[0][2], z[0][3], 16), a1m1 = mrg(z[1][2], z[1][3], 16);
        float a0m2 = mrg(z[0][4], z[0][5], 16), a1m2 = mrg(z[1][4], z[1][5], 16);
        float a0m3 = mrg(z[0][6], z[0][7], 16), a1m3 = mrg(z[1][6], z[1][7], 16);
        float a0n0 = mrg(a0m0, a0m1, 8), a1n0 = mrg(a1m0, a1m1, 8);
        float a0n1 = mrg(a0m2, a0m3, 8), a1n1 = mrg(a1m2, a1m3, 8);
        f0 = mrg(a0n0, a0n1, 4);  f1 = mrg(a1n0, a1n1, 4);
        f0 += __shfl_xor_sync(FULL_MASK, f0, 2); f1 += __shfl_xor_sync(FULL_MASK, f1, 2);
        f0 += __shfl_xor_sync(FULL_MASK, f0, 1); f1 += __shfl_xor_sync(FULL_MASK, f1, 1);
    }
    float g0[NQ], g1[NQ];
    #pragma unroll
    for (int q = 0; q < NQ; q++) {
        const int sl = srcLane(q);
        g0[q] = __shfl_sync(FULL_MASK, f0, sl);
        g1[q] = __shfl_sync(FULL_MASK, f1, sl);
    }

    // ---- output head ----
    if (lane < NCLS) {
        float o0 = s_ob[lane], o1 = o0;
        #pragma unroll
        for (int q = 0; q < NQ; q++) {
            float w = s_ow[lane * NQ + q];
            o0 += g0[q] * w;
            o1 += g1[q] * w;
        }
        out[(size_t)b0 * NCLS + lane] = o0;
        if (v1) out[(size_t)b1 * NCLS + lane] = o1;
    }
}

extern "C" void kernel_launch(void* const* d_in, const int* in_sizes, int n_in,
                              void* d_out, int out_size) {
    const float* x      = (const float*)d_in[0];
    const float* proj_w = (const float*)d_in[1];
    const float* qnn_w  = (const float*)d_in[2];
    const float* out_w  = (const float*)d_in[3];
    const float* out_b  = (const float*)d_in[4];
    float* out = (float*)d_out;

    int B = in_sizes[0] / FDIM;            // 8192
    int blocks = (B + 15) / 16;            // 512 blocks = 4096 warps, 2 elems each
    qiskit_head_kernel<<<blocks, 256>>>(x, proj_w, qnn_w, out_w, out_b, out, B);
}

// round 7
// speedup vs baseline: 1.4171x; 1.4171x over previous
#include <cuda_runtime.h>
#include <cstdint>

#define FULL_MASK 0xFFFFFFFFu
#define NQ 8
#define DEPTH 3
#define FDIM 512
#define NCLS 10

typedef unsigned long long u64;

// ---- packed f32x2 helpers (sm_100+: FFMA2/FADD2/FMUL2) ----
__device__ __forceinline__ u64 pk2(float lo, float hi) {
    u64 r; asm("mov.b64 %0,{%1,%2};" : "=l"(r) : "f"(lo), "f"(hi)); return r;
}
__device__ __forceinline__ void up2(u64 v, float& lo, float& hi) {
    asm("mov.b64 {%0,%1},%2;" : "=f"(lo), "=f"(hi) : "l"(v));
}
__device__ __forceinline__ u64 fma2_(u64 a, u64 b, u64 c) {
    u64 d; asm("fma.rn.f32x2 %0,%1,%2,%3;" : "=l"(d) : "l"(a), "l"(b), "l"(c)); return d;
}
__device__ __forceinline__ u64 mul2_(u64 a, u64 b) {
    u64 d; asm("mul.rn.f32x2 %0,%1,%2;" : "=l"(d) : "l"(a), "l"(b)); return d;
}
__device__ __forceinline__ u64 add2_(u64 a, u64 b) {
    u64 d; asm("add.rn.f32x2 %0,%1,%2;" : "=l"(d) : "l"(a), "l"(b)); return d;
}
__device__ __forceinline__ u64 neg2_(u64 a) { return a ^ 0x8000000080000000ULL; }
__device__ __forceinline__ u64 bc2(float c) { return pk2(c, c); }

// Deferred-CNOT masks (GF(2)); layout p = (lane<<3)|r, r = qubit bits 0..2.
// parity table for 3-bit values: 0x96
template<int PM, int W>
__device__ __forceinline__ void gateP(u64 AR[8], u64 AI[8], float4 A, float4 Bv, int lane)
{
    constexpr int pr = PM & 7, pl = PM >> 3, wr = W & 7, wl = W >> 3;
    bool bL = (wl != 0) && ((__popc(lane & wl) & 1) != 0);
    // u00=(A.x,A.y) u01=(A.z,A.w) u10=(Bv.x,Bv.y) u11=(Bv.z,Bv.w)
    float oAx = bL ? Bv.z : A.x,  oAy = bL ? Bv.w : A.y;
    float pAx = bL ? Bv.x : A.z,  pAy = bL ? Bv.y : A.w;
    float oBx = bL ? A.x : Bv.z,  oBy = bL ? A.y : Bv.w;
    float pBx = bL ? A.z : Bv.x,  pBy = bL ? A.w : Bv.y;
    u64 oAx2 = bc2(oAx), oAy2 = bc2(oAy), pAx2 = bc2(pAx), pAy2 = bc2(pAy);
    u64 oBx2 = bc2(oBx), oBy2 = bc2(oBy), pBx2 = bc2(pBx), pBy2 = bc2(pBy);
    u64 oAyn = neg2_(oAy2), pAyn = neg2_(pAy2), oByn = neg2_(oBy2), pByn = neg2_(pBy2);

    if constexpr (pl == 0) {
        #pragma unroll
        for (int r = 0; r < 8; r++) {
            if (((0x96 >> (r & wr)) & 1) == 0) {   // pair base (compile-time)
                const int r1 = r ^ pr;
                u64 a0r = AR[r], a0i = AI[r], a1r = AR[r1], a1i = AI[r1];
                AR[r]  = fma2_(pAyn, a1i, fma2_(pAx2, a1r, fma2_(oAyn, a0i, mul2_(oAx2, a0r))));
                AI[r]  = fma2_(pAy2, a1r, fma2_(pAx2, a1i, fma2_(oAy2, a0r, mul2_(oAx2, a0i))));
                AR[r1] = fma2_(pByn, a0i, fma2_(pBx2, a0r, fma2_(oByn, a1i, mul2_(oBx2, a1r))));
                AI[r1] = fma2_(pBy2, a0r, fma2_(pBx2, a0i, fma2_(oBy2, a1r, mul2_(oBx2, a1i))));
            }
        }
    } else if constexpr (pr == 0) {
        #pragma unroll
        for (int r = 0; r < 8; r++) {
            u64 tr = __shfl_xor_sync(FULL_MASK, AR[r], pl);
            u64 ti = __shfl_xor_sync(FULL_MASK, AI[r], pl);
            const bool pb = ((0x96 >> (r & wr)) & 1) != 0;   // compile-time
            u64 ox = pb ? oBx2 : oAx2, oy = pb ? oBy2 : oAy2, oyn = pb ? oByn : oAyn;
            u64 px = pb ? pBx2 : pAx2, py = pb ? pBy2 : pAy2, pyn = pb ? pByn : pAyn;
            u64 nr = fma2_(pyn, ti, fma2_(px, tr, fma2_(oyn, AI[r], mul2_(ox, AR[r]))));
            u64 ni = fma2_(py, tr, fma2_(px, ti, fma2_(oy, AR[r], mul2_(ox, AI[r]))));
            AR[r] = nr; AI[r] = ni;
        }
    } else {
        #pragma unroll
        for (int r = 0; r < 8; r++) {
            if (r < (r ^ pr)) {                   // compile-time pair rep
                const int r1 = r ^ pr;
                u64 sr0 = __shfl_xor_sync(FULL_MASK, AR[r1], pl);
                u64 si0 = __shfl_xor_sync(FULL_MASK, AI[r1], pl);
                u64 sr1 = __shfl_xor_sync(FULL_MASK, AR[r],  pl);
                u64 si1 = __shfl_xor_sync(FULL_MASK, AI[r],  pl);
                const bool pb0 = ((0x96 >> (r  & wr)) & 1) != 0;
                const bool pb1 = ((0x96 >> (r1 & wr)) & 1) != 0;
                u64 o0x = pb0?oBx2:oAx2, o0y = pb0?oBy2:oAy2, o0yn = pb0?oByn:oAyn;
                u64 p0x = pb0?pBx2:pAx2, p0y = pb0?pBy2:pAy2, p0yn = pb0?pByn:pAyn;
                u64 o1x = pb1?oBx2:oAx2, o1y = pb1?oBy2:oAy2, o1yn = pb1?oByn:oAyn;
                u64 p1x = pb1?pBx2:pAx2, p1y = pb1?pBy2:pAy2, p1yn = pb1?pByn:pAyn;
                u64 nr0 = fma2_(p0yn, si0, fma2_(p0x, sr0, fma2_(o0yn, AI[r],  mul2_(o0x, AR[r]))));
                u64 ni0 = fma2_(p0y,  sr0, fma2_(p0x, si0, fma2_(o0y,  AR[r],  mul2_(o0x, AI[r]))));
                u64 nr1 = fma2_(p1yn, si1, fma2_(p1x, sr1, fma2_(o1yn, AI[r1], mul2_(o1x, AR[r1]))));
                u64 ni1 = fma2_(p1y,  sr1, fma2_(p1x, si1, fma2_(o1y,  AR[r1], mul2_(o1x, AI[r1]))));
                AR[r] = nr0; AI[r] = ni0; AR[r1] = nr1; AI[r1] = ni1;
            }
        }
    }
}

__global__ void __launch_bounds__(256, 3) qiskit_head_kernel(
    const float* __restrict__ x,       // (B, 512)
    const float* __restrict__ proj_w,  // (8, 512)
    const float* __restrict__ qnn_w,   // (72,)
    const float* __restrict__ out_w,   // (10, 8)
    const float* __restrict__ out_b,   // (10,)
    float* __restrict__ out,           // (B, 10)
    int B)
{
    __shared__ __align__(16) float s_pw[NQ * FDIM];   // 16 KB
    __shared__ float4 s_g4[DEPTH * NQ][2];
    __shared__ float  s_ow[NCLS * NQ];
    __shared__ float  s_ob[NCLS];

    const int tid  = threadIdx.x;
    const int lane = tid & 31;
    const int warp = tid >> 5;

    #pragma unroll 4
    for (int i = tid; i < NQ * FDIM; i += 256) s_pw[i] = proj_w[i];
    if (tid < NCLS * NQ) s_ow[tid] = out_w[tid];
    if (tid < NCLS)      s_ob[tid] = out_b[tid];
    if (tid < DEPTH * NQ) {
        float w0 = qnn_w[tid * 3 + 0];
        float w1 = qnn_w[tid * 3 + 1];
        float w2 = qnn_w[tid * 3 + 2];
        float c0, s0, c1, s1, c2, s2;
        sincosf(0.5f * w0, &s0, &c0);
        sincosf(0.5f * w1, &s1, &c1);
        sincosf(0.5f * w2, &s2, &c2);
        float2 A00 = { c1 * c0,  s1 * s0};
        float2 A01 = {-s1 * c0, -c1 * s0};
        float2 A10 = { s1 * c0, -c1 * s0};
        float2 A11 = { c1 * c0, -s1 * s0};
        float2 g00 = make_float2(c2 * A00.x + s2 * A10.y, c2 * A00.y - s2 * A10.x);
        float2 g01 = make_float2(c2 * A01.x + s2 * A11.y, c2 * A01.y - s2 * A11.x);
        float2 g10 = make_float2(c2 * A10.x + s2 * A00.y, c2 * A10.y - s2 * A00.x);
        float2 g11 = make_float2(c2 * A11.x + s2 * A01.y, c2 * A11.y - s2 * A01.x);
        s_g4[tid][0] = make_float4(g00.x, g00.y, g01.x, g01.y);
        s_g4[tid][1] = make_float4(g10.x, g10.y, g11.x, g11.y);
    }
    __syncthreads();

    auto mrgP = [&](u64 a, u64 b, int dist) -> u64 {
        u64 c = (lane & dist) ? b : a;
        u64 d = (lane & dist) ? a : b;
        return add2_(c, __shfl_xor_sync(FULL_MASK, d, dist));
    };
    auto srcLane = [](int q) { return ((q & 1) << 4) | (((q >> 1) & 1) << 3) | (((q >> 2) & 1) << 2); };

    const int b0 = (blockIdx.x * 8 + warp) * 2;   // elem A (lo half)
    const int b1 = b0 + 1;                        // elem B (hi half)
    if (b0 >= B) return;
    const bool v1 = (b1 < B);

    // ---- projection (dual scalar accumulate, packed reduce) ----
    float acc[2][NQ];
    #pragma unroll
    for (int e = 0; e < 2; e++)
        #pragma unroll
        for (int q = 0; q < NQ; q++) acc[e][q] = 0.f;

    const float4* xr0 = (const float4*)(x + (size_t)b0 * FDIM);
    const float4* xr1 = (const float4*)(x + (size_t)(v1 ? b1 : b0) * FDIM);
    #pragma unroll
    for (int ch = 0; ch < 4; ch++) {
        float4 xv0 = xr0[ch * 32 + lane];
        float4 xv1 = xr1[ch * 32 + lane];
        #pragma unroll
        for (int q = 0; q < NQ; q++) {
            float4 wv = *(const float4*)&s_pw[q * FDIM + ch * 128 + lane * 4];
            acc[0][q] += xv0.x*wv.x + xv0.y*wv.y + xv0.z*wv.z + xv0.w*wv.w;
            acc[1][q] += xv1.x*wv.x + xv1.y*wv.y + xv1.z*wv.z + xv1.w*wv.w;
        }
    }
    u64 CV, SV;
    {
        u64 ap[8];
        #pragma unroll
        for (int q = 0; q < NQ; q++) ap[q] = pk2(acc[0][q], acc[1][q]);
        u64 m0 = mrgP(ap[0], ap[1], 16), m1 = mrgP(ap[2], ap[3], 16);
        u64 m2 = mrgP(ap[4], ap[5], 16), m3 = mrgP(ap[6], ap[7], 16);
        u64 n0 = mrgP(m0, m1, 8), n1 = mrgP(m2, m3, 8);
        u64 F  = mrgP(n0, n1, 4);
        F = add2_(F, __shfl_xor_sync(FULL_MASK, F, 2));
        F = add2_(F, __shfl_xor_sync(FULL_MASK, F, 1));
        float dA, dB; up2(F, dA, dB);
        float hA = tanhf(dA) * 0.78539816339744830962f;
        float hB = tanhf(dB) * 0.78539816339744830962f;
        float cA, sA, cB, sB;
        __sincosf(hA, &sA, &cA);
        __sincosf(hB, &sB, &cB);
        CV = pk2(cA, cB); SV = pk2(sA, sB);
    }

    // ---- state after encoding + layer-0 gates: product state (packed) ----
    u64 Lr = pk2(1.f, 1.f), Li = 0ULL;
    #pragma unroll
    for (int k = 0; k < 5; k++) {
        const int q = k + 3;
        u64 cq = __shfl_sync(FULL_MASK, CV, srcLane(q));
        u64 sq = __shfl_sync(FULL_MASK, SV, srcLane(q));
        float4 V = s_g4[q][(lane >> k) & 1];
        u64 wx = fma2_(bc2(V.z), sq, mul2_(bc2(V.x), cq));
        u64 wy = fma2_(bc2(V.w), sq, mul2_(bc2(V.y), cq));
        u64 nLr = fma2_(neg2_(Li), wy, mul2_(Lr, wx));
        u64 nLi = fma2_(Li, wx, mul2_(Lr, wy));
        Lr = nLr; Li = nLi;
    }
    u64 AR[8], AI[8];
    {
        u64 cq = __shfl_sync(FULL_MASK, CV, srcLane(0));
        u64 sq = __shfl_sync(FULL_MASK, SV, srcLane(0));
        float4 A0 = s_g4[0][0], B0 = s_g4[0][1];
        u64 a0x = fma2_(bc2(A0.z), sq, mul2_(bc2(A0.x), cq));
        u64 a0y = fma2_(bc2(A0.w), sq, mul2_(bc2(A0.y), cq));
        u64 b0x = fma2_(bc2(B0.z), sq, mul2_(bc2(B0.x), cq));
        u64 b0y = fma2_(bc2(B0.w), sq, mul2_(bc2(B0.y), cq));
        u64 Lin = neg2_(Li);
        AR[0] = fma2_(Lin, a0y, mul2_(Lr, a0x));  AI[0] = fma2_(Li, a0x, mul2_(Lr, a0y));
        AR[1] = fma2_(Lin, b0y, mul2_(Lr, b0x));  AI[1] = fma2_(Li, b0x, mul2_(Lr, b0y));
    }
    {
        u64 cq = __shfl_sync(FULL_MASK, CV, srcLane(1));
        u64 sq = __shfl_sync(FULL_MASK, SV, srcLane(1));
        float4 A1 = s_g4[1][0], B1 = s_g4[1][1];
        u64 a1x = fma2_(bc2(A1.z), sq, mul2_(bc2(A1.x), cq));
        u64 a1y = fma2_(bc2(A1.w), sq, mul2_(bc2(A1.y), cq));
        u64 b1x = fma2_(bc2(B1.z), sq, mul2_(bc2(B1.x), cq));
        u64 b1y = fma2_(bc2(B1.w), sq, mul2_(bc2(B1.y), cq));
        u64 a1yn = neg2_(a1y), b1yn = neg2_(b1y);
        #pragma unroll
        for (int r = 0; r < 2; r++) {
            u64 tr = AR[r], ti = AI[r];
            AR[r + 2] = fma2_(b1yn, ti, mul2_(tr, b1x));  AI[r + 2] = fma2_(b1y, tr, mul2_(ti, b1x));
            AR[r]     = fma2_(a1yn, ti, mul2_(tr, a1x));  AI[r]     = fma2_(a1y, tr, mul2_(ti, a1x));
        }
    }
    {
        u64 cq = __shfl_sync(FULL_MASK, CV, srcLane(2));
        u64 sq = __shfl_sync(FULL_MASK, SV, srcLane(2));
        float4 A2 = s_g4[2][0], B2 = s_g4[2][1];
        u64 a2x = fma2_(bc2(A2.z), sq, mul2_(bc2(A2.x), cq));
        u64 a2y = fma2_(bc2(A2.w), sq, mul2_(bc2(A2.y), cq));
        u64 b2x = fma2_(bc2(B2.z), sq, mul2_(bc2(B2.x), cq));
        u64 b2y = fma2_(bc2(B2.w), sq, mul2_(bc2(B2.y), cq));
        u64 a2yn = neg2_(a2y), b2yn = neg2_(b2y);
        #pragma unroll
        for (int r = 0; r < 4; r++) {
            u64 tr = AR[r], ti = AI[r];
            AR[r + 4] = fma2_(b2yn, ti, mul2_(tr, b2x));  AI[r + 4] = fma2_(b2y, tr, mul2_(ti, b2x));
            AR[r]     = fma2_(a2yn, ti, mul2_(tr, a2x));  AI[r]     = fma2_(a2y, tr, mul2_(ti, a2x));
        }
    }

    // ---- layers 1,2 with deferred-CNOT masks (packed 2 elems) ----
    #define GATE(idx, PMv, Wv) gateP<PMv, Wv>(AR, AI, s_g4[idx][0], s_g4[idx][1], lane)
    // layer 1 (phi = C)
    GATE(8,  0x03, 0xFE); GATE(9,  0x06, 0x03); GATE(10, 0x0C, 0x07); GATE(11, 0x18, 0x0F);
    GATE(12, 0x30, 0x1F); GATE(13, 0x60, 0x3F); GATE(14, 0xC0, 0x7F); GATE(15, 0x83, 0xFF);
    // layer 2 (phi = C^2)
    GATE(16, 0x05, 0xAB); GATE(17, 0x0A, 0xFD); GATE(18, 0x14, 0xFA); GATE(19, 0x28, 0xF5);
    GATE(20, 0x50, 0xEA); GATE(21, 0xA0, 0xD5); GATE(22, 0x43, 0xAA); GATE(23, 0x86, 0x55);
    #undef GATE

    // ---- PauliZ via Walsh-Hadamard of |amp|^2 (phi = C^3), packed ----
    u64 S[8];
    #pragma unroll
    for (int r = 0; r < 8; r++) S[r] = fma2_(AI[r], AI[r], mul2_(AR[r], AR[r]));
    #pragma unroll
    for (int st = 0; st < 3; st++) {
        const int d = 1 << st;
        #pragma unroll
        for (int r = 0; r < 8; r++) {
            if (!(r & d)) {
                u64 a = add2_(S[r], S[r + d]);
                u64 b = add2_(S[r], neg2_(S[r + d]));
                S[r] = a; S[r + d] = b;
            }
        }
    }
    auto sgp = [&](int wl, u64 v) -> u64 { return (__popc(lane & wl) & 1) ? neg2_(v) : v; };
    u64 z0 = sgp(0x06, S[2]), z1 = sgp(0x0A, S[6]);
    u64 z2 = sgp(0x15, S[4]), z3 = sgp(0x0B, S[1]);
    u64 z4 = sgp(0x16, S[3]), z5 = sgp(0x0C, S[6]);
    u64 z6 = sgp(0x19, S[4]), z7 = sgp(0x13, S[1]);
    u64 m0 = mrgP(z0, z1, 16), m1 = mrgP(z2, z3, 16);
    u64 m2 = mrgP(z4, z5, 16), m3 = mrgP(z6, z7, 16);
    u64 n0 = mrgP(m0, m1, 8),  n1 = mrgP(m2, m3, 8);
    u64 F  = mrgP(n0, n1, 4);
    F = add2_(F, __shfl_xor_sync(FULL_MASK, F, 2));
    F = add2_(F, __shfl_xor_sync(FULL_MASK, F, 1));
    u64 gq[NQ];
    #pragma unroll
    for (int q = 0; q < NQ; q++) gq[q] = __shfl_sync(FULL_MASK, F, srcLane(q));

    // ---- output head ----
    if (lane < NCLS) {
        float o0 = s_ob[lane], o1 = o0;
        #pragma unroll
        for (int q = 0; q < NQ; q++) {
            float w = s_ow[lane * NQ + q];
            float gA, gB; up2(gq[q], gA, gB);
            o0 += gA * w;
            o1 += gB * w;
        }
        out[(size_t)b0 * NCLS + lane] = o0;
        if (v1) out[(size_t)b1 * NCLS + lane] = o1;
    }
}

extern "C" void kernel_launch(void* const* d_in, const int* in_sizes, int n_in,
                              void* d_out, int out_size) {
    const float* x      = (const float*)d_in[0];
    const float* proj_w = (const float*)d_in[1];
    const float* qnn_w  = (const float*)d_in[2];
    const float* out_w  = (const float*)d_in[3];
    const float* out_b  = (const float*)d_in[4];
    float* out = (float*)d_out;

    int B = in_sizes[0] / FDIM;            // 8192
    int blocks = (B + 15) / 16;            // 512 blocks = 4096 warps, 2 packed elems each
    qiskit_head_kernel<<<blocks, 256>>>(x, proj_w, qnn_w, out_w, out_b, out, B);
}

// round 8
// speedup vs baseline: 1.4189x; 1.0013x over previous
#include <cuda_runtime.h>
#include <cstdint>

#define FULL_MASK 0xFFFFFFFFu
#define NQ 8
#define DEPTH 3
#define FDIM 512
#define NCLS 10

typedef unsigned long long u64;

// ---- packed f32x2 helpers (sm_100+: FFMA2/FADD2/FMUL2) ----
__device__ __forceinline__ u64 pk2(float lo, float hi) {
    u64 r; asm("mov.b64 %0,{%1,%2};" : "=l"(r) : "f"(lo), "f"(hi)); return r;
}
__device__ __forceinline__ void up2(u64 v, float& lo, float& hi) {
    asm("mov.b64 {%0,%1},%2;" : "=f"(lo), "=f"(hi) : "l"(v));
}
__device__ __forceinline__ u64 fma2_(u64 a, u64 b, u64 c) {
    u64 d; asm("fma.rn.f32x2 %0,%1,%2,%3;" : "=l"(d) : "l"(a), "l"(b), "l"(c)); return d;
}
__device__ __forceinline__ u64 mul2_(u64 a, u64 b) {
    u64 d; asm("mul.rn.f32x2 %0,%1,%2;" : "=l"(d) : "l"(a), "l"(b)); return d;
}
__device__ __forceinline__ u64 add2_(u64 a, u64 b) {
    u64 d; asm("add.rn.f32x2 %0,%1,%2;" : "=l"(d) : "l"(a), "l"(b)); return d;
}
__device__ __forceinline__ u64 neg2_(u64 a) { return a ^ 0x8000000080000000ULL; }
__device__ __forceinline__ u64 bc2(float c) { return pk2(c, c); }

// Deferred-CNOT masks (GF(2)); layout p = (lane<<3)|r, r = qubit bits 0..2.
// parity table for 3-bit values: 0x96
// Register diet: only 8 base coefficient packs live; negation via inline XOR.
template<int PM, int W>
__device__ __forceinline__ void gateP(u64 AR[8], u64 AI[8], float4 A, float4 Bv, int lane)
{
    constexpr int pr = PM & 7, pl = PM >> 3, wr = W & 7, wl = W >> 3;
    bool bL = (wl != 0) && ((__popc(lane & wl) & 1) != 0);
    // u00=(A.x,A.y) u01=(A.z,A.w) u10=(Bv.x,Bv.y) u11=(Bv.z,Bv.w)
    u64 oAx2 = bc2(bL ? Bv.z : A.x), oAy2 = bc2(bL ? Bv.w : A.y);
    u64 pAx2 = bc2(bL ? Bv.x : A.z), pAy2 = bc2(bL ? Bv.y : A.w);
    u64 oBx2 = bc2(bL ? A.x : Bv.z), oBy2 = bc2(bL ? A.y : Bv.w);
    u64 pBx2 = bc2(bL ? A.z : Bv.x), pBy2 = bc2(bL ? A.w : Bv.y);

    if constexpr (pl == 0) {
        #pragma unroll
        for (int r = 0; r < 8; r++) {
            if (((0x96 >> (r & wr)) & 1) == 0) {   // pair base (compile-time)
                const int r1 = r ^ pr;
                u64 a0r = AR[r], a0i = AI[r], a1r = AR[r1], a1i = AI[r1];
                AR[r]  = fma2_(neg2_(pAy2), a1i, fma2_(pAx2, a1r, fma2_(neg2_(oAy2), a0i, mul2_(oAx2, a0r))));
                AI[r]  = fma2_(pAy2, a1r, fma2_(pAx2, a1i, fma2_(oAy2, a0r, mul2_(oAx2, a0i))));
                AR[r1] = fma2_(neg2_(pBy2), a0i, fma2_(pBx2, a0r, fma2_(neg2_(oBy2), a1i, mul2_(oBx2, a1r))));
                AI[r1] = fma2_(pBy2, a0r, fma2_(pBx2, a0i, fma2_(oBy2, a1r, mul2_(oBx2, a1i))));
            }
        }
    } else if constexpr (pr == 0) {
        #pragma unroll
        for (int r = 0; r < 8; r++) {
            u64 tr = __shfl_xor_sync(FULL_MASK, AR[r], pl);
            u64 ti = __shfl_xor_sync(FULL_MASK, AI[r], pl);
            const bool pb = ((0x96 >> (r & wr)) & 1) != 0;   // compile-time
            u64 ox = pb ? oBx2 : oAx2, oy = pb ? oBy2 : oAy2;
            u64 px = pb ? pBx2 : pAx2, py = pb ? pBy2 : pAy2;
            u64 nr = fma2_(neg2_(py), ti, fma2_(px, tr, fma2_(neg2_(oy), AI[r], mul2_(ox, AR[r]))));
            u64 ni = fma2_(py, tr, fma2_(px, ti, fma2_(oy, AR[r], mul2_(ox, AI[r]))));
            AR[r] = nr; AI[r] = ni;
        }
    } else {
        #pragma unroll
        for (int r = 0; r < 8; r++) {
            if (r < (r ^ pr)) {                   // compile-time pair rep
                const int r1 = r ^ pr;
                u64 sr0 = __shfl_xor_sync(FULL_MASK, AR[r1], pl);
                u64 si0 = __shfl_xor_sync(FULL_MASK, AI[r1], pl);
                u64 sr1 = __shfl_xor_sync(FULL_MASK, AR[r],  pl);
                u64 si1 = __shfl_xor_sync(FULL_MASK, AI[r],  pl);
                const bool pb0 = ((0x96 >> (r  & wr)) & 1) != 0;
                const bool pb1 = ((0x96 >> (r1 & wr)) & 1) != 0;
                u64 o0x = pb0?oBx2:oAx2, o0y = pb0?oBy2:oAy2;
                u64 p0x = pb0?pBx2:pAx2, p0y = pb0?pBy2:pAy2;
                u64 o1x = pb1?oBx2:oAx2, o1y = pb1?oBy2:oAy2;
                u64 p1x = pb1?pBx2:pAx2, p1y = pb1?pBy2:pAy2;
                u64 nr0 = fma2_(neg2_(p0y), si0, fma2_(p0x, sr0, fma2_(neg2_(o0y), AI[r],  mul2_(o0x, AR[r]))));
                u64 ni0 = fma2_(p0y,  sr0, fma2_(p0x, si0, fma2_(o0y,  AR[r],  mul2_(o0x, AI[r]))));
                u64 nr1 = fma2_(neg2_(p1y), si1, fma2_(p1x, sr1, fma2_(neg2_(o1y), AI[r1], mul2_(o1x, AR[r1]))));
                u64 ni1 = fma2_(p1y,  sr1, fma2_(p1x, si1, fma2_(o1y,  AR[r1], mul2_(o1x, AI[r1]))));
                AR[r] = nr0; AI[r] = ni0; AR[r1] = nr1; AI[r1] = ni1;
            }
        }
    }
}

__global__ void __launch_bounds__(256, 4) qiskit_head_kernel(
    const float* __restrict__ x,       // (B, 512)
    const float* __restrict__ proj_w,  // (8, 512)
    const float* __restrict__ qnn_w,   // (72,)
    const float* __restrict__ out_w,   // (10, 8)
    const float* __restrict__ out_b,   // (10,)
    float* __restrict__ out,           // (B, 10)
    int B)
{
    __shared__ __align__(16) float s_pw[NQ * FDIM];   // 16 KB
    __shared__ float4 s_g4[DEPTH * NQ][2];
    __shared__ float  s_ow[NCLS * NQ];
    __shared__ float  s_ob[NCLS];

    const int tid  = threadIdx.x;
    const int lane = tid & 31;
    const int warp = tid >> 5;

    #pragma unroll 4
    for (int i = tid; i < NQ * FDIM; i += 256) s_pw[i] = proj_w[i];
    if (tid < NCLS * NQ) s_ow[tid] = out_w[tid];
    if (tid < NCLS)      s_ob[tid] = out_b[tid];
    if (tid < DEPTH * NQ) {
        float w0 = qnn_w[tid * 3 + 0];
        float w1 = qnn_w[tid * 3 + 1];
        float w2 = qnn_w[tid * 3 + 2];
        float c0, s0, c1, s1, c2, s2;
        sincosf(0.5f * w0, &s0, &c0);
        sincosf(0.5f * w1, &s1, &c1);
        sincosf(0.5f * w2, &s2, &c2);
        float2 A00 = { c1 * c0,  s1 * s0};
        float2 A01 = {-s1 * c0, -c1 * s0};
        float2 A10 = { s1 * c0, -c1 * s0};
        float2 A11 = { c1 * c0, -s1 * s0};
        float2 g00 = make_float2(c2 * A00.x + s2 * A10.y, c2 * A00.y - s2 * A10.x);
        float2 g01 = make_float2(c2 * A01.x + s2 * A11.y, c2 * A01.y - s2 * A11.x);
        float2 g10 = make_float2(c2 * A10.x + s2 * A00.y, c2 * A10.y - s2 * A00.x);
        float2 g11 = make_float2(c2 * A11.x + s2 * A01.y, c2 * A11.y - s2 * A01.x);
        s_g4[tid][0] = make_float4(g00.x, g00.y, g01.x, g01.y);
        s_g4[tid][1] = make_float4(g10.x, g10.y, g11.x, g11.y);
    }
    __syncthreads();

    auto mrgP = [&](u64 a, u64 b, int dist) -> u64 {
        u64 c = (lane & dist) ? b : a;
        u64 d = (lane & dist) ? a : b;
        return add2_(c, __shfl_xor_sync(FULL_MASK, d, dist));
    };
    auto srcLane = [](int q) { return ((q & 1) << 4) | (((q >> 1) & 1) << 3) | (((q >> 2) & 1) << 2); };

    const int b0 = (blockIdx.x * 8 + warp) * 2;   // elem A (lo half)
    const int b1 = b0 + 1;                        // elem B (hi half)
    if (b0 >= B) return;
    const bool v1 = (b1 < B);

    // ---- projection (dual scalar accumulate, packed reduce) ----
    float acc[2][NQ];
    #pragma unroll
    for (int e = 0; e < 2; e++)
        #pragma unroll
        for (int q = 0; q < NQ; q++) acc[e][q] = 0.f;

    const float4* xr0 = (const float4*)(x + (size_t)b0 * FDIM);
    const float4* xr1 = (const float4*)(x + (size_t)(v1 ? b1 : b0) * FDIM);
    #pragma unroll
    for (int ch = 0; ch < 4; ch++) {
        float4 xv0 = xr0[ch * 32 + lane];
        float4 xv1 = xr1[ch * 32 + lane];
        #pragma unroll
        for (int q = 0; q < NQ; q++) {
            float4 wv = *(const float4*)&s_pw[q * FDIM + ch * 128 + lane * 4];
            acc[0][q] += xv0.x*wv.x + xv0.y*wv.y + xv0.z*wv.z + xv0.w*wv.w;
            acc[1][q] += xv1.x*wv.x + xv1.y*wv.y + xv1.z*wv.z + xv1.w*wv.w;
        }
    }
    u64 CV, SV;
    {
        u64 ap[8];
        #pragma unroll
        for (int q = 0; q < NQ; q++) ap[q] = pk2(acc[0][q], acc[1][q]);
        u64 m0 = mrgP(ap[0], ap[1], 16), m1 = mrgP(ap[2], ap[3], 16);
        u64 m2 = mrgP(ap[4], ap[5], 16), m3 = mrgP(ap[6], ap[7], 16);
        u64 n0 = mrgP(m0, m1, 8), n1 = mrgP(m2, m3, 8);
        u64 F  = mrgP(n0, n1, 4);
        F = add2_(F, __shfl_xor_sync(FULL_MASK, F, 2));
        F = add2_(F, __shfl_xor_sync(FULL_MASK, F, 1));
        float dA, dB; up2(F, dA, dB);
        float hA = tanhf(dA) * 0.78539816339744830962f;
        float hB = tanhf(dB) * 0.78539816339744830962f;
        float cA, sA, cB, sB;
        __sincosf(hA, &sA, &cA);
        __sincosf(hB, &sB, &cB);
        CV = pk2(cA, cB); SV = pk2(sA, sB);
    }

    // ---- state after encoding + layer-0 gates: product state (packed) ----
    u64 Lr = pk2(1.f, 1.f), Li = 0ULL;
    #pragma unroll
    for (int k = 0; k < 5; k++) {
        const int q = k + 3;
        u64 cq = __shfl_sync(FULL_MASK, CV, srcLane(q));
        u64 sq = __shfl_sync(FULL_MASK, SV, srcLane(q));
        float4 V = s_g4[q][(lane >> k) & 1];
        u64 wx = fma2_(bc2(V.z), sq, mul2_(bc2(V.x), cq));
        u64 wy = fma2_(bc2(V.w), sq, mul2_(bc2(V.y), cq));
        u64 nLr = fma2_(neg2_(Li), wy, mul2_(Lr, wx));
        u64 nLi = fma2_(Li, wx, mul2_(Lr, wy));
        Lr = nLr; Li = nLi;
    }
    u64 AR[8], AI[8];
    {
        u64 cq = __shfl_sync(FULL_MASK, CV, srcLane(0));
        u64 sq = __shfl_sync(FULL_MASK, SV, srcLane(0));
        float4 A0 = s_g4[0][0], B0 = s_g4[0][1];
        u64 a0x = fma2_(bc2(A0.z), sq, mul2_(bc2(A0.x), cq));
        u64 a0y = fma2_(bc2(A0.w), sq, mul2_(bc2(A0.y), cq));
        u64 b0x = fma2_(bc2(B0.z), sq, mul2_(bc2(B0.x), cq));
        u64 b0y = fma2_(bc2(B0.w), sq, mul2_(bc2(B0.y), cq));
        AR[0] = fma2_(neg2_(Li), a0y, mul2_(Lr, a0x));  AI[0] = fma2_(Li, a0x, mul2_(Lr, a0y));
        AR[1] = fma2_(neg2_(Li), b0y, mul2_(Lr, b0x));  AI[1] = fma2_(Li, b0x, mul2_(Lr, b0y));
    }
    {
        u64 cq = __shfl_sync(FULL_MASK, CV, srcLane(1));
        u64 sq = __shfl_sync(FULL_MASK, SV, srcLane(1));
        float4 A1 = s_g4[1][0], B1 = s_g4[1][1];
        u64 a1x = fma2_(bc2(A1.z), sq, mul2_(bc2(A1.x), cq));
        u64 a1y = fma2_(bc2(A1.w), sq, mul2_(bc2(A1.y), cq));
        u64 b1x = fma2_(bc2(B1.z), sq, mul2_(bc2(B1.x), cq));
        u64 b1y = fma2_(bc2(B1.w), sq, mul2_(bc2(B1.y), cq));
        #pragma unroll
        for (int r = 0; r < 2; r++) {
            u64 tr = AR[r], ti = AI[r];
            AR[r + 2] = fma2_(neg2_(b1y), ti, mul2_(tr, b1x));  AI[r + 2] = fma2_(b1y, tr, mul2_(ti, b1x));
            AR[r]     = fma2_(neg2_(a1y), ti, mul2_(tr, a1x));  AI[r]     = fma2_(a1y, tr, mul2_(ti, a1x));
        }
    }
    {
        u64 cq = __shfl_sync(FULL_MASK, CV, srcLane(2));
        u64 sq = __shfl_sync(FULL_MASK, SV, srcLane(2));
        float4 A2 = s_g4[2][0], B2 = s_g4[2][1];
        u64 a2x = fma2_(bc2(A2.z), sq, mul2_(bc2(A2.x), cq));
        u64 a2y = fma2_(bc2(A2.w), sq, mul2_(bc2(A2.y), cq));
        u64 b2x = fma2_(bc2(B2.z), sq, mul2_(bc2(B2.x), cq));
        u64 b2y = fma2_(bc2(B2.w), sq, mul2_(bc2(B2.y), cq));
        #pragma unroll
        for (int r = 0; r < 4; r++) {
            u64 tr = AR[r], ti = AI[r];
            AR[r + 4] = fma2_(neg2_(b2y), ti, mul2_(tr, b2x));  AI[r + 4] = fma2_(b2y, tr, mul2_(ti, b2x));
            AR[r]     = fma2_(neg2_(a2y), ti, mul2_(tr, a2x));  AI[r]     = fma2_(a2y, tr, mul2_(ti, a2x));
        }
    }

    // ---- layers 1,2 with deferred-CNOT masks (packed 2 elems) ----
    #define GATE(idx, PMv, Wv) gateP<PMv, Wv>(AR, AI, s_g4[idx][0], s_g4[idx][1], lane)
    // layer 1 (phi = C)
    GATE(8,  0x03, 0xFE); GATE(9,  0x06, 0x03); GATE(10, 0x0C, 0x07); GATE(11, 0x18, 0x0F);
    GATE(12, 0x30, 0x1F); GATE(13, 0x60, 0x3F); GATE(14, 0xC0, 0x7F); GATE(15, 0x83, 0xFF);
    // layer 2 (phi = C^2)
    GATE(16, 0x05, 0xAB); GATE(17, 0x0A, 0xFD); GATE(18, 0x14, 0xFA); GATE(19, 0x28, 0xF5);
    GATE(20, 0x50, 0xEA); GATE(21, 0xA0, 0xD5); GATE(22, 0x43, 0xAA); GATE(23, 0x86, 0x55);
    #undef GATE

    // ---- PauliZ via Walsh-Hadamard of |amp|^2 (phi = C^3), packed ----
    u64 S[8];
    #pragma unroll
    for (int r = 0; r < 8; r++) S[r] = fma2_(AI[r], AI[r], mul2_(AR[r], AR[r]));
    #pragma unroll
    for (int st = 0; st < 3; st++) {
        const int d = 1 << st;
        #pragma unroll
        for (int r = 0; r < 8; r++) {
            if (!(r & d)) {
                u64 a = add2_(S[r], S[r + d]);
                u64 b = add2_(S[r], neg2_(S[r + d]));
                S[r] = a; S[r + d] = b;
            }
        }
    }
    auto sgp = [&](int wl, u64 v) -> u64 { return (__popc(lane & wl) & 1) ? neg2_(v) : v; };
    u64 z0 = sgp(0x06, S[2]), z1 = sgp(0x0A, S[6]);
    u64 z2 = sgp(0x15, S[4]), z3 = sgp(0x0B, S[1]);
    u64 z4 = sgp(0x16, S[3]), z5 = sgp(0x0C, S[6]);
    u64 z6 = sgp(0x19, S[4]), z7 = sgp(0x13, S[1]);
    u64 m0 = mrgP(z0, z1, 16), m1 = mrgP(z2, z3, 16);
    u64 m2 = mrgP(z4, z5, 16), m3 = mrgP(z6, z7, 16);
    u64 n0 = mrgP(m0, m1, 8),  n1 = mrgP(m2, m3, 8);
    u64 F  = mrgP(n0, n1, 4);
    F = add2_(F, __shfl_xor_sync(FULL_MASK, F, 2));
    F = add2_(F, __shfl_xor_sync(FULL_MASK, F, 1));
    u64 gq[NQ];
    #pragma unroll
    for (int q = 0; q < NQ; q++) gq[q] = __shfl_sync(FULL_MASK, F, srcLane(q));

    // ---- output head ----
    if (lane < NCLS) {
        float o0 = s_ob[lane], o1 = o0;
        #pragma unroll
        for (int q = 0; q < NQ; q++) {
            float w = s_ow[lane * NQ + q];
            float gA, gB; up2(gq[q], gA, gB);
            o0 += gA * w;
            o1 += gB * w;
        }
        out[(size_t)b0 * NCLS + lane] = o0;
        if (v1) out[(size_t)b1 * NCLS + lane] = o1;
    }
}

extern "C" void kernel_launch(void* const* d_in, const int* in_sizes, int n_in,
                              void* d_out, int out_size) {
    const float* x      = (const float*)d_in[0];
    const float* proj_w = (const float*)d_in[1];
    const float* qnn_w  = (const float*)d_in[2];
    const float* out_w  = (const float*)d_in[3];
    const float* out_b  = (const float*)d_in[4];
    float* out = (float*)d_out;

    int B = in_sizes[0] / FDIM;            // 8192
    int blocks = (B + 15) / 16;            // 512 blocks = 4096 warps, 2 packed elems each
    qiskit_head_kernel<<<blocks, 256>>>(x, proj_w, qnn_w, out_w, out_b, out, B);
}

// round 9
// speedup vs baseline: 1.5261x; 1.0755x over previous
#include <cuda_runtime.h>
#include <cstdint>

#define FULL_MASK 0xFFFFFFFFu
#define NQ 8
#define DEPTH 3
#define FDIM 512
#define NCLS 10
#define BTHREADS 128

typedef unsigned long long u64;

// ---- packed f32x2 helpers (sm_100+: FFMA2/FADD2/FMUL2) ----
__device__ __forceinline__ u64 pk2(float lo, float hi) {
    u64 r; asm("mov.b64 %0,{%1,%2};" : "=l"(r) : "f"(lo), "f"(hi)); return r;
}
__device__ __forceinline__ void up2(u64 v, float& lo, float& hi) {
    asm("mov.b64 {%0,%1},%2;" : "=f"(lo), "=f"(hi) : "l"(v));
}
__device__ __forceinline__ u64 fma2_(u64 a, u64 b, u64 c) {
    u64 d; asm("fma.rn.f32x2 %0,%1,%2,%3;" : "=l"(d) : "l"(a), "l"(b), "l"(c)); return d;
}
__device__ __forceinline__ u64 mul2_(u64 a, u64 b) {
    u64 d; asm("mul.rn.f32x2 %0,%1,%2;" : "=l"(d) : "l"(a), "l"(b)); return d;
}
__device__ __forceinline__ u64 add2_(u64 a, u64 b) {
    u64 d; asm("add.rn.f32x2 %0,%1,%2;" : "=l"(d) : "l"(a), "l"(b)); return d;
}
__device__ __forceinline__ u64 neg2_(u64 a) { return a ^ 0x8000000080000000ULL; }
__device__ __forceinline__ u64 bc2(float c) { return pk2(c, c); }

// Deferred-CNOT masks (GF(2)); layout p = (lane<<3)|r, r = qubit bits 0..2.
// parity table for 3-bit values: 0x96
template<int PM, int W>
__device__ __forceinline__ void gateP(u64 AR[8], u64 AI[8], float4 A, float4 Bv, int lane)
{
    constexpr int pr = PM & 7, pl = PM >> 3, wr = W & 7, wl = W >> 3;
    bool bL = (wl != 0) && ((__popc(lane & wl) & 1) != 0);
    // u00=(A.x,A.y) u01=(A.z,A.w) u10=(Bv.x,Bv.y) u11=(Bv.z,Bv.w)
    u64 oAx2 = bc2(bL ? Bv.z : A.x), oAy2 = bc2(bL ? Bv.w : A.y);
    u64 pAx2 = bc2(bL ? Bv.x : A.z), pAy2 = bc2(bL ? Bv.y : A.w);
    u64 oBx2 = bc2(bL ? A.x : Bv.z), oBy2 = bc2(bL ? A.y : Bv.w);
    u64 pBx2 = bc2(bL ? A.z : Bv.x), pBy2 = bc2(bL ? A.w : Bv.y);

    if constexpr (pl == 0) {
        #pragma unroll
        for (int r = 0; r < 8; r++) {
            if (((0x96 >> (r & wr)) & 1) == 0) {   // pair base (compile-time)
                const int r1 = r ^ pr;
                u64 a0r = AR[r], a0i = AI[r], a1r = AR[r1], a1i = AI[r1];
                AR[r]  = fma2_(neg2_(pAy2), a1i, fma2_(pAx2, a1r, fma2_(neg2_(oAy2), a0i, mul2_(oAx2, a0r))));
                AI[r]  = fma2_(pAy2, a1r, fma2_(pAx2, a1i, fma2_(oAy2, a0r, mul2_(oAx2, a0i))));
                AR[r1] = fma2_(neg2_(pBy2), a0i, fma2_(pBx2, a0r, fma2_(neg2_(oBy2), a1i, mul2_(oBx2, a1r))));
                AI[r1] = fma2_(pBy2, a0r, fma2_(pBx2, a0i, fma2_(oBy2, a1r, mul2_(oBx2, a1i))));
            }
        }
    } else if constexpr (pr == 0) {
        #pragma unroll
        for (int r = 0; r < 8; r++) {
            u64 tr = __shfl_xor_sync(FULL_MASK, AR[r], pl);
            u64 ti = __shfl_xor_sync(FULL_MASK, AI[r], pl);
            const bool pb = ((0x96 >> (r & wr)) & 1) != 0;   // compile-time
            u64 ox = pb ? oBx2 : oAx2, oy = pb ? oBy2 : oAy2;
            u64 px = pb ? pBx2 : pAx2, py = pb ? pBy2 : pAy2;
            u64 nr = fma2_(neg2_(py), ti, fma2_(px, tr, fma2_(neg2_(oy), AI[r], mul2_(ox, AR[r]))));
            u64 ni = fma2_(py, tr, fma2_(px, ti, fma2_(oy, AR[r], mul2_(ox, AI[r]))));
            AR[r] = nr; AI[r] = ni;
        }
    } else {
        #pragma unroll
        for (int r = 0; r < 8; r++) {
            if (r < (r ^ pr)) {                   // compile-time pair rep
                const int r1 = r ^ pr;
                u64 sr0 = __shfl_xor_sync(FULL_MASK, AR[r1], pl);
                u64 si0 = __shfl_xor_sync(FULL_MASK, AI[r1], pl);
                u64 sr1 = __shfl_xor_sync(FULL_MASK, AR[r],  pl);
                u64 si1 = __shfl_xor_sync(FULL_MASK, AI[r],  pl);
                const bool pb0 = ((0x96 >> (r  & wr)) & 1) != 0;
                const bool pb1 = ((0x96 >> (r1 & wr)) & 1) != 0;
                u64 o0x = pb0?oBx2:oAx2, o0y = pb0?oBy2:oAy2;
                u64 p0x = pb0?pBx2:pAx2, p0y = pb0?pBy2:pAy2;
                u64 o1x = pb1?oBx2:oAx2, o1y = pb1?oBy2:oAy2;
                u64 p1x = pb1?pBx2:pAx2, p1y = pb1?pBy2:pAy2;
                u64 nr0 = fma2_(neg2_(p0y), si0, fma2_(p0x, sr0, fma2_(neg2_(o0y), AI[r],  mul2_(o0x, AR[r]))));
                u64 ni0 = fma2_(p0y,  sr0, fma2_(p0x, si0, fma2_(o0y,  AR[r],  mul2_(o0x, AI[r]))));
                u64 nr1 = fma2_(neg2_(p1y), si1, fma2_(p1x, sr1, fma2_(neg2_(o1y), AI[r1], mul2_(o1x, AR[r1]))));
                u64 ni1 = fma2_(p1y,  sr1, fma2_(p1x, si1, fma2_(o1y,  AR[r1], mul2_(o1x, AI[r1]))));
                AR[r] = nr0; AI[r] = ni0; AR[r1] = nr1; AI[r1] = ni1;
            }
        }
    }
}

__global__ void __launch_bounds__(BTHREADS, 8) qiskit_head_kernel(
    const float* __restrict__ x,       // (B, 512)
    const float* __restrict__ proj_w,  // (8, 512)
    const float* __restrict__ qnn_w,   // (72,)
    const float* __restrict__ out_w,   // (10, 8)
    const float* __restrict__ out_b,   // (10,)
    float* __restrict__ out,           // (B, 10)
    int B)
{
    __shared__ __align__(16) float s_pw[NQ * FDIM];   // 16 KB
    __shared__ float4 s_g4[DEPTH * NQ][2];
    __shared__ float  s_ow[NCLS * NQ];
    __shared__ float  s_ob[NCLS];

    const int tid  = threadIdx.x;
    const int lane = tid & 31;
    const int warp = tid >> 5;

    #pragma unroll 8
    for (int i = tid; i < NQ * FDIM; i += BTHREADS) s_pw[i] = proj_w[i];
    if (tid < NCLS * NQ) s_ow[tid] = out_w[tid];
    if (tid < NCLS)      s_ob[tid] = out_b[tid];
    if (tid < DEPTH * NQ) {
        float w0 = qnn_w[tid * 3 + 0];
        float w1 = qnn_w[tid * 3 + 1];
        float w2 = qnn_w[tid * 3 + 2];
        float c0, s0, c1, s1, c2, s2;
        sincosf(0.5f * w0, &s0, &c0);
        sincosf(0.5f * w1, &s1, &c1);
        sincosf(0.5f * w2, &s2, &c2);
        float2 A00 = { c1 * c0,  s1 * s0};
        float2 A01 = {-s1 * c0, -c1 * s0};
        float2 A10 = { s1 * c0, -c1 * s0};
        float2 A11 = { c1 * c0, -s1 * s0};
        float2 g00 = make_float2(c2 * A00.x + s2 * A10.y, c2 * A00.y - s2 * A10.x);
        float2 g01 = make_float2(c2 * A01.x + s2 * A11.y, c2 * A01.y - s2 * A11.x);
        float2 g10 = make_float2(c2 * A10.x + s2 * A00.y, c2 * A10.y - s2 * A00.x);
        float2 g11 = make_float2(c2 * A11.x + s2 * A01.y, c2 * A11.y - s2 * A01.x);
        s_g4[tid][0] = make_float4(g00.x, g00.y, g01.x, g01.y);
        s_g4[tid][1] = make_float4(g10.x, g10.y, g11.x, g11.y);
    }
    __syncthreads();

    auto mrgP = [&](u64 a, u64 b, int dist) -> u64 {
        u64 c = (lane & dist) ? b : a;
        u64 d = (lane & dist) ? a : b;
        return add2_(c, __shfl_xor_sync(FULL_MASK, d, dist));
    };
    auto srcLane = [](int q) { return ((q & 1) << 4) | (((q >> 1) & 1) << 3) | (((q >> 2) & 1) << 2); };

    const int b0 = (blockIdx.x * 4 + warp) * 2;   // elem A (lo half)
    const int b1 = b0 + 1;                        // elem B (hi half)
    if (b0 >= B) return;
    const bool v1 = (b1 < B);

    // ---- projection (dual scalar accumulate, packed reduce) ----
    float acc[2][NQ];
    #pragma unroll
    for (int e = 0; e < 2; e++)
        #pragma unroll
        for (int q = 0; q < NQ; q++) acc[e][q] = 0.f;

    const float4* xr0 = (const float4*)(x + (size_t)b0 * FDIM);
    const float4* xr1 = (const float4*)(x + (size_t)(v1 ? b1 : b0) * FDIM);
    #pragma unroll
    for (int ch = 0; ch < 4; ch++) {
        float4 xv0 = xr0[ch * 32 + lane];
        float4 xv1 = xr1[ch * 32 + lane];
        #pragma unroll
        for (int q = 0; q < NQ; q++) {
            float4 wv = *(const float4*)&s_pw[q * FDIM + ch * 128 + lane * 4];
            acc[0][q] += xv0.x*wv.x + xv0.y*wv.y + xv0.z*wv.z + xv0.w*wv.w;
            acc[1][q] += xv1.x*wv.x + xv1.y*wv.y + xv1.z*wv.z + xv1.w*wv.w;
        }
    }
    u64 CV, SV;
    {
        u64 ap[8];
        #pragma unroll
        for (int q = 0; q < NQ; q++) ap[q] = pk2(acc[0][q], acc[1][q]);
        u64 m0 = mrgP(ap[0], ap[1], 16), m1 = mrgP(ap[2], ap[3], 16);
        u64 m2 = mrgP(ap[4], ap[5], 16), m3 = mrgP(ap[6], ap[7], 16);
        u64 n0 = mrgP(m0, m1, 8), n1 = mrgP(m2, m3, 8);
        u64 F  = mrgP(n0, n1, 4);
        F = add2_(F, __shfl_xor_sync(FULL_MASK, F, 2));
        F = add2_(F, __shfl_xor_sync(FULL_MASK, F, 1));
        float dA, dB; up2(F, dA, dB);
        float hA = tanhf(dA) * 0.78539816339744830962f;
        float hB = tanhf(dB) * 0.78539816339744830962f;
        float cA, sA, cB, sB;
        __sincosf(hA, &sA, &cA);
        __sincosf(hB, &sB, &cB);
        CV = pk2(cA, cB); SV = pk2(sA, sB);
    }

    // ---- state after encoding + layer-0 gates: product state (packed) ----
    u64 Lr = pk2(1.f, 1.f), Li = 0ULL;
    #pragma unroll
    for (int k = 0; k < 5; k++) {
        const int q = k + 3;
        u64 cq = __shfl_sync(FULL_MASK, CV, srcLane(q));
        u64 sq = __shfl_sync(FULL_MASK, SV, srcLane(q));
        float4 V = s_g4[q][(lane >> k) & 1];
        u64 wx = fma2_(bc2(V.z), sq, mul2_(bc2(V.x), cq));
        u64 wy = fma2_(bc2(V.w), sq, mul2_(bc2(V.y), cq));
        u64 nLr = fma2_(neg2_(Li), wy, mul2_(Lr, wx));
        u64 nLi = fma2_(Li, wx, mul2_(Lr, wy));
        Lr = nLr; Li = nLi;
    }
    u64 AR[8], AI[8];
    {
        u64 cq = __shfl_sync(FULL_MASK, CV, srcLane(0));
        u64 sq = __shfl_sync(FULL_MASK, SV, srcLane(0));
        float4 A0 = s_g4[0][0], B0 = s_g4[0][1];
        u64 a0x = fma2_(bc2(A0.z), sq, mul2_(bc2(A0.x), cq));
        u64 a0y = fma2_(bc2(A0.w), sq, mul2_(bc2(A0.y), cq));
        u64 b0x = fma2_(bc2(B0.z), sq, mul2_(bc2(B0.x), cq));
        u64 b0y = fma2_(bc2(B0.w), sq, mul2_(bc2(B0.y), cq));
        AR[0] = fma2_(neg2_(Li), a0y, mul2_(Lr, a0x));  AI[0] = fma2_(Li, a0x, mul2_(Lr, a0y));
        AR[1] = fma2_(neg2_(Li), b0y, mul2_(Lr, b0x));  AI[1] = fma2_(Li, b0x, mul2_(Lr, b0y));
    }
    {
        u64 cq = __shfl_sync(FULL_MASK, CV, srcLane(1));
        u64 sq = __shfl_sync(FULL_MASK, SV, srcLane(1));
        float4 A1 = s_g4[1][0], B1 = s_g4[1][1];
        u64 a1x = fma2_(bc2(A1.z), sq, mul2_(bc2(A1.x), cq));
        u64 a1y = fma2_(bc2(A1.w), sq, mul2_(bc2(A1.y), cq));
        u64 b1x = fma2_(bc2(B1.z), sq, mul2_(bc2(B1.x), cq));
        u64 b1y = fma2_(bc2(B1.w), sq, mul2_(bc2(B1.y), cq));
        #pragma unroll
        for (int r = 0; r < 2; r++) {
            u64 tr = AR[r], ti = AI[r];
            AR[r + 2] = fma2_(neg2_(b1y), ti, mul2_(tr, b1x));  AI[r + 2] = fma2_(b1y, tr, mul2_(ti, b1x));
            AR[r]     = fma2_(neg2_(a1y), ti, mul2_(tr, a1x));  AI[r]     = fma2_(a1y, tr, mul2_(ti, a1x));
        }
    }
    {
        u64 cq = __shfl_sync(FULL_MASK, CV, srcLane(2));
        u64 sq = __shfl_sync(FULL_MASK, SV, srcLane(2));
        float4 A2 = s_g4[2][0], B2 = s_g4[2][1];
        u64 a2x = fma2_(bc2(A2.z), sq, mul2_(bc2(A2.x), cq));
        u64 a2y = fma2_(bc2(A2.w), sq, mul2_(bc2(A2.y), cq));
        u64 b2x = fma2_(bc2(B2.z), sq, mul2_(bc2(B2.x), cq));
        u64 b2y = fma2_(bc2(B2.w), sq, mul2_(bc2(B2.y), cq));
        #pragma unroll
        for (int r = 0; r < 4; r++) {
            u64 tr = AR[r], ti = AI[r];
            AR[r + 4] = fma2_(neg2_(b2y), ti, mul2_(tr, b2x));  AI[r + 4] = fma2_(b2y, tr, mul2_(ti, b2x));
            AR[r]     = fma2_(neg2_(a2y), ti, mul2_(tr, a2x));  AI[r]     = fma2_(a2y, tr, mul2_(ti, a2x));
        }
    }

    // ---- layers 1,2 with deferred-CNOT masks (packed 2 elems) ----
    #define GATE(idx, PMv, Wv) gateP<PMv, Wv>(AR, AI, s_g4[idx][0], s_g4[idx][1], lane)
    // layer 1 (phi = C)
    GATE(8,  0x03, 0xFE); GATE(9,  0x06, 0x03); GATE(10, 0x0C, 0x07); GATE(11, 0x18, 0x0F);
    GATE(12, 0x30, 0x1F); GATE(13, 0x60, 0x3F); GATE(14, 0xC0, 0x7F); GATE(15, 0x83, 0xFF);
    // layer 2 (phi = C^2)
    GATE(16, 0x05, 0xAB); GATE(17, 0x0A, 0xFD); GATE(18, 0x14, 0xFA); GATE(19, 0x28, 0xF5);
    GATE(20, 0x50, 0xEA); GATE(21, 0xA0, 0xD5); GATE(22, 0x43, 0xAA); GATE(23, 0x86, 0x55);
    #undef GATE

    // ---- PauliZ via Walsh-Hadamard of |amp|^2 (phi = C^3), packed ----
    u64 S[8];
    #pragma unroll
    for (int r = 0; r < 8; r++) S[r] = fma2_(AI[r], AI[r], mul2_(AR[r], AR[r]));
    #pragma unroll
    for (int st = 0; st < 3; st++) {
        const int d = 1 << st;
        #pragma unroll
        for (int r = 0; r < 8; r++) {
            if (!(r & d)) {
                u64 a = add2_(S[r], S[r + d]);
                u64 b = add2_(S[r], neg2_(S[r + d]));
                S[r] = a; S[r + d] = b;
            }
        }
    }
    auto sgp = [&](int wl, u64 v) -> u64 { return (__popc(lane & wl) & 1) ? neg2_(v) : v; };
    u64 z0 = sgp(0x06, S[2]), z1 = sgp(0x0A, S[6]);
    u64 z2 = sgp(0x15, S[4]), z3 = sgp(0x0B, S[1]);
    u64 z4 = sgp(0x16, S[3]), z5 = sgp(0x0C, S[6]);
    u64 z6 = sgp(0x19, S[4]), z7 = sgp(0x13, S[1]);
    u64 m0 = mrgP(z0, z1, 16), m1 = mrgP(z2, z3, 16);
    u64 m2 = mrgP(z4, z5, 16), m3 = mrgP(z6, z7, 16);
    u64 n0 = mrgP(m0, m1, 8),  n1 = mrgP(m2, m3, 8);
    u64 F  = mrgP(n0, n1, 4);
    F = add2_(F, __shfl_xor_sync(FULL_MASK, F, 2));
    F = add2_(F, __shfl_xor_sync(FULL_MASK, F, 1));
    u64 gq[NQ];
    #pragma unroll
    for (int q = 0; q < NQ; q++) gq[q] = __shfl_sync(FULL_MASK, F, srcLane(q));

    // ---- output head ----
    if (lane < NCLS) {
        float o0 = s_ob[lane], o1 = o0;
        #pragma unroll
        for (int q = 0; q < NQ; q++) {
            float w = s_ow[lane * NQ + q];
            float gA, gB; up2(gq[q], gA, gB);
            o0 += gA * w;
            o1 += gB * w;
        }
        out[(size_t)b0 * NCLS + lane] = o0;
        if (v1) out[(size_t)b1 * NCLS + lane] = o1;
    }
}

extern "C" void kernel_launch(void* const* d_in, const int* in_sizes, int n_in,
                              void* d_out, int out_size) {
    const float* x      = (const float*)d_in[0];
    const float* proj_w = (const float*)d_in[1];
    const float* qnn_w  = (const float*)d_in[2];
    const float* out_w  = (const float*)d_in[3];
    const float* out_b  = (const float*)d_in[4];
    float* out = (float*)d_out;

    int B = in_sizes[0] / FDIM;            // 8192
    int blocks = (B + 7) / 8;              // 1024 blocks x 4 warps x 2 elems = 8192
    qiskit_head_kernel<<<blocks, BTHREADS>>>(x, proj_w, qnn_w, out_w, out_b, out, B);
}

// round 10
// speedup vs baseline: 1.5452x; 1.0125x over previous
#include <cuda_runtime.h>
#include <cstdint>

#define FULL_MASK 0xFFFFFFFFu
#define NQ 8
#define DEPTH 3
#define FDIM 512
#define NCLS 10
#define BTHREADS 128
#define MAXB 8192

typedef unsigned long long u64;

// ---- device-global scratch (allocation-free) ----
__device__ float2 g_cs[MAXB * NQ];      // (cos, sin) of half-angle per (b, q)
__device__ float4 g_gates[DEPTH * NQ][2];

// ---- packed f32x2 helpers ----
__device__ __forceinline__ u64 pk2(float lo, float hi) {
    u64 r; asm("mov.b64 %0,{%1,%2};" : "=l"(r) : "f"(lo), "f"(hi)); return r;
}
__device__ __forceinline__ void up2(u64 v, float& lo, float& hi) {
    asm("mov.b64 {%0,%1},%2;" : "=f"(lo), "=f"(hi) : "l"(v));
}
__device__ __forceinline__ u64 fma2_(u64 a, u64 b, u64 c) {
    u64 d; asm("fma.rn.f32x2 %0,%1,%2,%3;" : "=l"(d) : "l"(a), "l"(b), "l"(c)); return d;
}
__device__ __forceinline__ u64 mul2_(u64 a, u64 b) {
    u64 d; asm("mul.rn.f32x2 %0,%1,%2;" : "=l"(d) : "l"(a), "l"(b)); return d;
}
__device__ __forceinline__ u64 add2_(u64 a, u64 b) {
    u64 d; asm("add.rn.f32x2 %0,%1,%2;" : "=l"(d) : "l"(a), "l"(b)); return d;
}
__device__ __forceinline__ u64 neg2_(u64 a) { return a ^ 0x8000000080000000ULL; }
__device__ __forceinline__ u64 bc2(float c) { return pk2(c, c); }

// ============================================================
// Kernel 1: projection + tanh + half-angle sincos -> g_cs ; gates -> g_gates
// ============================================================
__global__ void __launch_bounds__(BTHREADS, 8) proj_kernel(
    const float* __restrict__ x,       // (B, 512)
    const float* __restrict__ proj_w,  // (8, 512)
    const float* __restrict__ qnn_w,   // (72,)
    int B)
{
    const int tid  = threadIdx.x;
    const int lane = tid & 31;
    const int warp = tid >> 5;

    // gates (block 0 only)
    if (blockIdx.x == 0 && tid < DEPTH * NQ) {
        float w0 = qnn_w[tid * 3 + 0];
        float w1 = qnn_w[tid * 3 + 1];
        float w2 = qnn_w[tid * 3 + 2];
        float c0, s0, c1, s1, c2, s2;
        sincosf(0.5f * w0, &s0, &c0);
        sincosf(0.5f * w1, &s1, &c1);
        sincosf(0.5f * w2, &s2, &c2);
        float2 A00 = { c1 * c0,  s1 * s0};
        float2 A01 = {-s1 * c0, -c1 * s0};
        float2 A10 = { s1 * c0, -c1 * s0};
        float2 A11 = { c1 * c0, -s1 * s0};
        float2 q00 = make_float2(c2 * A00.x + s2 * A10.y, c2 * A00.y - s2 * A10.x);
        float2 q01 = make_float2(c2 * A01.x + s2 * A11.y, c2 * A01.y - s2 * A11.x);
        float2 q10 = make_float2(c2 * A10.x + s2 * A00.y, c2 * A10.y - s2 * A00.x);
        float2 q11 = make_float2(c2 * A11.x + s2 * A01.y, c2 * A11.y - s2 * A01.x);
        g_gates[tid][0] = make_float4(q00.x, q00.y, q01.x, q01.y);
        g_gates[tid][1] = make_float4(q10.x, q10.y, q11.x, q11.y);
    }

    const int b0 = (blockIdx.x * 4 + warp) * 2;
    const int b1 = b0 + 1;
    if (b0 >= B) return;
    const bool v1 = (b1 < B);

    float acc[2][NQ];
    #pragma unroll
    for (int e = 0; e < 2; e++)
        #pragma unroll
        for (int q = 0; q < NQ; q++) acc[e][q] = 0.f;

    const float4* xr0 = (const float4*)(x + (size_t)b0 * FDIM);
    const float4* xr1 = (const float4*)(x + (size_t)(v1 ? b1 : b0) * FDIM);
    #pragma unroll
    for (int ch = 0; ch < 4; ch++) {
        float4 xv0 = xr0[ch * 32 + lane];
        float4 xv1 = xr1[ch * 32 + lane];
        #pragma unroll
        for (int q = 0; q < NQ; q++) {
            float4 wv = __ldg((const float4*)&proj_w[q * FDIM + ch * 128 + lane * 4]);
            acc[0][q] += xv0.x*wv.x + xv0.y*wv.y + xv0.z*wv.z + xv0.w*wv.w;
            acc[1][q] += xv1.x*wv.x + xv1.y*wv.y + xv1.z*wv.z + xv1.w*wv.w;
        }
    }
    auto mrgP = [&](u64 a, u64 b, int dist) -> u64 {
        u64 c = (lane & dist) ? b : a;
        u64 d = (lane & dist) ? a : b;
        return add2_(c, __shfl_xor_sync(FULL_MASK, d, dist));
    };
    u64 ap[8];
    #pragma unroll
    for (int q = 0; q < NQ; q++) ap[q] = pk2(acc[0][q], acc[1][q]);
    u64 m0 = mrgP(ap[0], ap[1], 16), m1 = mrgP(ap[2], ap[3], 16);
    u64 m2 = mrgP(ap[4], ap[5], 16), m3 = mrgP(ap[6], ap[7], 16);
    u64 n0 = mrgP(m0, m1, 8), n1 = mrgP(m2, m3, 8);
    u64 F  = mrgP(n0, n1, 4);
    F = add2_(F, __shfl_xor_sync(FULL_MASK, F, 2));
    F = add2_(F, __shfl_xor_sync(FULL_MASK, F, 1));

    if ((lane & 3) == 0) {
        // this lane's q (inverse of srcLane map)
        const int q = ((lane >> 4) & 1) | (((lane >> 3) & 1) << 1) | (((lane >> 2) & 1) << 2);
        float dA, dB; up2(F, dA, dB);
        float hA = tanhf(dA) * 0.78539816339744830962f;
        float hB = tanhf(dB) * 0.78539816339744830962f;
        float cA, sA, cB, sB;
        __sincosf(hA, &sA, &cA);
        __sincosf(hB, &sB, &cB);
        g_cs[b0 * NQ + q] = make_float2(cA, sA);
        if (v1) g_cs[b1 * NQ + q] = make_float2(cB, sB);
    }
}

// ============================================================
// Kernel 2: circuit (deferred-CNOT, packed 2 elems) + head
// ============================================================
// parity table for 3-bit values: 0x96
template<int PM, int W>
__device__ __forceinline__ void gateP(u64 AR[8], u64 AI[8], float4 A, float4 Bv, int lane)
{
    constexpr int pr = PM & 7, pl = PM >> 3, wr = W & 7, wl = W >> 3;
    bool bL = (wl != 0) && ((__popc(lane & wl) & 1) != 0);
    u64 oAx2 = bc2(bL ? Bv.z : A.x), oAy2 = bc2(bL ? Bv.w : A.y);
    u64 pAx2 = bc2(bL ? Bv.x : A.z), pAy2 = bc2(bL ? Bv.y : A.w);
    u64 oBx2 = bc2(bL ? A.x : Bv.z), oBy2 = bc2(bL ? A.y : Bv.w);
    u64 pBx2 = bc2(bL ? A.z : Bv.x), pBy2 = bc2(bL ? A.w : Bv.y);

    if constexpr (pl == 0) {
        #pragma unroll
        for (int r = 0; r < 8; r++) {
            if (((0x96 >> (r & wr)) & 1) == 0) {
                const int r1 = r ^ pr;
                u64 a0r = AR[r], a0i = AI[r], a1r = AR[r1], a1i = AI[r1];
                AR[r]  = fma2_(neg2_(pAy2), a1i, fma2_(pAx2, a1r, fma2_(neg2_(oAy2), a0i, mul2_(oAx2, a0r))));
                AI[r]  = fma2_(pAy2, a1r, fma2_(pAx2, a1i, fma2_(oAy2, a0r, mul2_(oAx2, a0i))));
                AR[r1] = fma2_(neg2_(pBy2), a0i, fma2_(pBx2, a0r, fma2_(neg2_(oBy2), a1i, mul2_(oBx2, a1r))));
                AI[r1] = fma2_(pBy2, a0r, fma2_(pBx2, a0i, fma2_(oBy2, a1r, mul2_(oBx2, a1i))));
            }
        }
    } else if constexpr (pr == 0) {
        #pragma unroll
        for (int r = 0; r < 8; r++) {
            u64 tr = __shfl_xor_sync(FULL_MASK, AR[r], pl);
            u64 ti = __shfl_xor_sync(FULL_MASK, AI[r], pl);
            const bool pb = ((0x96 >> (r & wr)) & 1) != 0;
            u64 ox = pb ? oBx2 : oAx2, oy = pb ? oBy2 : oAy2;
            u64 px = pb ? pBx2 : pAx2, py = pb ? pBy2 : pAy2;
            u64 nr = fma2_(neg2_(py), ti, fma2_(px, tr, fma2_(neg2_(oy), AI[r], mul2_(ox, AR[r]))));
            u64 ni = fma2_(py, tr, fma2_(px, ti, fma2_(oy, AR[r], mul2_(ox, AI[r]))));
            AR[r] = nr; AI[r] = ni;
        }
    } else {
        #pragma unroll
        for (int r = 0; r < 8; r++) {
            if (r < (r ^ pr)) {
                const int r1 = r ^ pr;
                u64 sr0 = __shfl_xor_sync(FULL_MASK, AR[r1], pl);
                u64 si0 = __shfl_xor_sync(FULL_MASK, AI[r1], pl);
                u64 sr1 = __shfl_xor_sync(FULL_MASK, AR[r],  pl);
                u64 si1 = __shfl_xor_sync(FULL_MASK, AI[r],  pl);
                const bool pb0 = ((0x96 >> (r  & wr)) & 1) != 0;
                const bool pb1 = ((0x96 >> (r1 & wr)) & 1) != 0;
                u64 o0x = pb0?oBx2:oAx2, o0y = pb0?oBy2:oAy2;
                u64 p0x = pb0?pBx2:pAx2, p0y = pb0?pBy2:pAy2;
                u64 o1x = pb1?oBx2:oAx2, o1y = pb1?oBy2:oAy2;
                u64 p1x = pb1?pBx2:pAx2, p1y = pb1?pBy2:pAy2;
                u64 nr0 = fma2_(neg2_(p0y), si0, fma2_(p0x, sr0, fma2_(neg2_(o0y), AI[r],  mul2_(o0x, AR[r]))));
                u64 ni0 = fma2_(p0y,  sr0, fma2_(p0x, si0, fma2_(o0y,  AR[r],  mul2_(o0x, AI[r]))));
                u64 nr1 = fma2_(neg2_(p1y), si1, fma2_(p1x, sr1, fma2_(neg2_(o1y), AI[r1], mul2_(o1x, AR[r1]))));
                u64 ni1 = fma2_(p1y,  sr1, fma2_(p1x, si1, fma2_(o1y,  AR[r1], mul2_(o1x, AI[r1]))));
                AR[r] = nr0; AI[r] = ni0; AR[r1] = nr1; AI[r1] = ni1;
            }
        }
    }
}

__global__ void __launch_bounds__(BTHREADS, 8) circuit_kernel(
    const float* __restrict__ out_w,   // (10, 8)
    const float* __restrict__ out_b,   // (10,)
    float* __restrict__ out,           // (B, 10)
    int B)
{
    __shared__ float4 s_g4[DEPTH * NQ][2];   // 768 B
    __shared__ float  s_ow[NCLS * NQ];
    __shared__ float  s_ob[NCLS];

    const int tid  = threadIdx.x;
    const int lane = tid & 31;
    const int warp = tid >> 5;

    if (tid < DEPTH * NQ * 2) ((float4*)s_g4)[tid] = ((const float4*)g_gates)[tid];
    if (tid < NCLS * NQ) s_ow[tid] = out_w[tid];
    if (tid < NCLS)      s_ob[tid] = out_b[tid];
    __syncthreads();

    auto mrgP = [&](u64 a, u64 b, int dist) -> u64 {
        u64 c = (lane & dist) ? b : a;
        u64 d = (lane & dist) ? a : b;
        return add2_(c, __shfl_xor_sync(FULL_MASK, d, dist));
    };
    auto srcLane = [](int q) { return ((q & 1) << 4) | (((q >> 1) & 1) << 3) | (((q >> 2) & 1) << 2); };

    const int b0 = (blockIdx.x * 4 + warp) * 2;
    const int b1 = b0 + 1;
    if (b0 >= B) return;
    const bool v1 = (b1 < B);

    // half-angle cos/sin for qubit (lane&7), both elems packed
    u64 CV, SV;
    {
        float2 csA = __ldg(&g_cs[b0 * NQ + (lane & 7)]);
        float2 csB = __ldg(&g_cs[(v1 ? b1 : b0) * NQ + (lane & 7)]);
        CV = pk2(csA.x, csB.x);
        SV = pk2(csA.y, csB.y);
    }

    // ---- product state (encoding + layer-0 gates); qubit q's c/s at lane q ----
    u64 Lr = pk2(1.f, 1.f), Li = 0ULL;
    #pragma unroll
    for (int k = 0; k < 5; k++) {
        const int q = k + 3;
        u64 cq = __shfl_sync(FULL_MASK, CV, q);
        u64 sq = __shfl_sync(FULL_MASK, SV, q);
        float4 V = s_g4[q][(lane >> k) & 1];
        u64 wx = fma2_(bc2(V.z), sq, mul2_(bc2(V.x), cq));
        u64 wy = fma2_(bc2(V.w), sq, mul2_(bc2(V.y), cq));
        u64 nLr = fma2_(neg2_(Li), wy, mul2_(Lr, wx));
        u64 nLi = fma2_(Li, wx, mul2_(Lr, wy));
        Lr = nLr; Li = nLi;
    }
    u64 AR[8], AI[8];
    {
        u64 cq = __shfl_sync(FULL_MASK, CV, 0);
        u64 sq = __shfl_sync(FULL_MASK, SV, 0);
        float4 A0 = s_g4[0][0], B0 = s_g4[0][1];
        u64 a0x = fma2_(bc2(A0.z), sq, mul2_(bc2(A0.x), cq));
        u64 a0y = fma2_(bc2(A0.w), sq, mul2_(bc2(A0.y), cq));
        u64 b0x = fma2_(bc2(B0.z), sq, mul2_(bc2(B0.x), cq));
        u64 b0y = fma2_(bc2(B0.w), sq, mul2_(bc2(B0.y), cq));
        AR[0] = fma2_(neg2_(Li), a0y, mul2_(Lr, a0x));  AI[0] = fma2_(Li, a0x, mul2_(Lr, a0y));
        AR[1] = fma2_(neg2_(Li), b0y, mul2_(Lr, b0x));  AI[1] = fma2_(Li, b0x, mul2_(Lr, b0y));
    }
    {
        u64 cq = __shfl_sync(FULL_MASK, CV, 1);
        u64 sq = __shfl_sync(FULL_MASK, SV, 1);
        float4 A1 = s_g4[1][0], B1 = s_g4[1][1];
        u64 a1x = fma2_(bc2(A1.z), sq, mul2_(bc2(A1.x), cq));
        u64 a1y = fma2_(bc2(A1.w), sq, mul2_(bc2(A1.y), cq));
        u64 b1x = fma2_(bc2(B1.z), sq, mul2_(bc2(B1.x), cq));
        u64 b1y = fma2_(bc2(B1.w), sq, mul2_(bc2(B1.y), cq));
        #pragma unroll
        for (int r = 0; r < 2; r++) {
            u64 tr = AR[r], ti = AI[r];
            AR[r + 2] = fma2_(neg2_(b1y), ti, mul2_(tr, b1x));  AI[r + 2] = fma2_(b1y, tr, mul2_(ti, b1x));
            AR[r]     = fma2_(neg2_(a1y), ti, mul2_(tr, a1x));  AI[r]     = fma2_(a1y, tr, mul2_(ti, a1x));
        }
    }
    {
        u64 cq = __shfl_sync(FULL_MASK, CV, 2);
        u64 sq = __shfl_sync(FULL_MASK, SV, 2);
        float4 A2 = s_g4[2][0], B2 = s_g4[2][1];
        u64 a2x = fma2_(bc2(A2.z), sq, mul2_(bc2(A2.x), cq));
        u64 a2y = fma2_(bc2(A2.w), sq, mul2_(bc2(A2.y), cq));
        u64 b2x = fma2_(bc2(B2.z), sq, mul2_(bc2(B2.x), cq));
        u64 b2y = fma2_(bc2(B2.w), sq, mul2_(bc2(B2.y), cq));
        #pragma unroll
        for (int r = 0; r < 4; r++) {
            u64 tr = AR[r], ti = AI[r];
            AR[r + 4] = fma2_(neg2_(b2y), ti, mul2_(tr, b2x));  AI[r + 4] = fma2_(b2y, tr, mul2_(ti, b2x));
            AR[r]     = fma2_(neg2_(a2y), ti, mul2_(tr, a2x));  AI[r]     = fma2_(a2y, tr, mul2_(ti, a2x));
        }
    }

    // ---- layers 1,2 with deferred-CNOT masks ----
    #define GATE(idx, PMv, Wv) gateP<PMv, Wv>(AR, AI, s_g4[idx][0], s_g4[idx][1], lane)
    GATE(8,  0x03, 0xFE); GATE(9,  0x06, 0x03); GATE(10, 0x0C, 0x07); GATE(11, 0x18, 0x0F);
    GATE(12, 0x30, 0x1F); GATE(13, 0x60, 0x3F); GATE(14, 0xC0, 0x7F); GATE(15, 0x83, 0xFF);
    GATE(16, 0x05, 0xAB); GATE(17, 0x0A, 0xFD); GATE(18, 0x14, 0xFA); GATE(19, 0x28, 0xF5);
    GATE(20, 0x50, 0xEA); GATE(21, 0xA0, 0xD5); GATE(22, 0x43, 0xAA); GATE(23, 0x86, 0x55);
    #undef GATE

    // ---- PauliZ via Walsh-Hadamard of |amp|^2 (phi = C^3), packed ----
    u64 S[8];
    #pragma unroll
    for (int r = 0; r < 8; r++) S[r] = fma2_(AI[r], AI[r], mul2_(AR[r], AR[r]));
    #pragma unroll
    for (int st = 0; st < 3; st++) {
        const int d = 1 << st;
        #pragma unroll
        for (int r = 0; r < 8; r++) {
            if (!(r & d)) {
                u64 a = add2_(S[r], S[r + d]);
                u64 b = add2_(S[r], neg2_(S[r + d]));
                S[r] = a; S[r + d] = b;
            }
        }
    }
    auto sgp = [&](int wl, u64 v) -> u64 { return (__popc(lane & wl) & 1) ? neg2_(v) : v; };
    u64 z0 = sgp(0x06, S[2]), z1 = sgp(0x0A, S[6]);
    u64 z2 = sgp(0x15, S[4]), z3 = sgp(0x0B, S[1]);
    u64 z4 = sgp(0x16, S[3]), z5 = sgp(0x0C, S[6]);
    u64 z6 = sgp(0x19, S[4]), z7 = sgp(0x13, S[1]);
    u64 m0 = mrgP(z0, z1, 16), m1 = mrgP(z2, z3, 16);
    u64 m2 = mrgP(z4, z5, 16), m3 = mrgP(z6, z7, 16);
    u64 n0 = mrgP(m0, m1, 8),  n1 = mrgP(m2, m3, 8);
    u64 F  = mrgP(n0, n1, 4);
    F = add2_(F, __shfl_xor_sync(FULL_MASK, F, 2));
    F = add2_(F, __shfl_xor_sync(FULL_MASK, F, 1));
    u64 gq[NQ];
    #pragma unroll
    for (int q = 0; q < NQ; q++) gq[q] = __shfl_sync(FULL_MASK, F, srcLane(q));

    // ---- output head ----
    if (lane < NCLS) {
        float o0 = s_ob[lane], o1 = o0;
        #pragma unroll
        for (int q = 0; q < NQ; q++) {
            float w = s_ow[lane * NQ + q];
            float gA, gB; up2(gq[q], gA, gB);
            o0 += gA * w;
            o1 += gB * w;
        }
        out[(size_t)b0 * NCLS + lane] = o0;
        if (v1) out[(size_t)b1 * NCLS + lane] = o1;
    }
}

extern "C" void kernel_launch(void* const* d_in, const int* in_sizes, int n_in,
                              void* d_out, int out_size) {
    const float* x      = (const float*)d_in[0];
    const float* proj_w = (const float*)d_in[1];
    const float* qnn_w  = (const float*)d_in[2];
    const float* out_w  = (const float*)d_in[3];
    const float* out_b  = (const float*)d_in[4];
    float* out = (float*)d_out;

    int B = in_sizes[0] / FDIM;            // 8192
    int blocks = (B + 7) / 8;              // 1024 blocks x 4 warps x 2 elems
    proj_kernel<<<blocks, BTHREADS>>>(x, proj_w, qnn_w, B);
    circuit_kernel<<<blocks, BTHREADS>>>(out_w, out_b, out, B);
}